// round 8
// baseline (speedup 1.0000x reference)
#include <cuda_runtime.h>
#include <math.h>

// Problem dims (fixed)
#define B_   128
#define T_   500
#define NI_  256
#define N_   256
#define M_   (B_*T_)
#define TBN_ ((size_t)T_*B_*N_)

// xw scratch, m-pair interleaved: ULL index p*256+n holds (xw[2p][n], xw[2p+1][n])
__device__ unsigned long long g_xw[(size_t)M_ * N_ / 2];

// Packed fp32x2 helpers
#define FFMA2(d, a, b, c) \
    asm("fma.rn.f32x2 %0, %1, %2, %3;" : "=l"(d) : "l"(a), "l"(b), "l"(c))
#define PACK2(d, s) \
    asm("mov.b64 %0, {%1, %1};" : "=l"(d) : "f"(s))
#define PACKAB(d, lo, hi) \
    asm("mov.b64 %0, {%1, %2};" : "=l"(d) : "f"(lo), "f"(hi))

// ===========================================================================
// Kernel 1: xw = x @ w_in. BM=128, BN=128, BK=16, 256 thr, 8m x 8n microtile.
// 2 CTAs/SM. (Measured ~155us; unchanged.)
// ===========================================================================
#define ASTRIDE 132
#define ASZ (2*16*ASTRIDE)
#define BSZ (2*16*128)
#define GEMM_SMEM ((ASZ + BSZ) * 4)

__global__ void __launch_bounds__(256, 2)
gemm_xw(const float* __restrict__ A, const float* __restrict__ W)
{
    extern __shared__ float gsm[];
    float* As = gsm;
    float* Bs = gsm + ASZ;

    const int t   = threadIdx.x;
    const int bm  = blockIdx.x << 7;
    const int bn0 = blockIdx.y << 7;
    const int tn  = t & 15;
    const int m0  = (t >> 4) << 3;

    const int amr[2] = { (t) >> 2, (t + 256) >> 2 };
    const int akc    = (t & 3) << 2;
    const int bkr[2] = { t >> 5, (t + 256) >> 5 };
    const int bnc    = (t & 31) << 2;

    unsigned long long acc[4][8];
#pragma unroll
    for (int e = 0; e < 4; e++)
#pragma unroll
        for (int j = 0; j < 8; j++) acc[e][j] = 0ull;

    float4 ra[2];

#pragma unroll
    for (int i = 0; i < 2; i++)
        ra[i] = *(const float4*)(A + (size_t)(bm + amr[i]) * NI_ + akc);
#pragma unroll
    for (int i = 0; i < 2; i++) {
        unsigned dst = (unsigned)__cvta_generic_to_shared(Bs + bkr[i] * 128 + bnc);
        asm volatile("cp.async.cg.shared.global [%0], [%1], 16;"
                     :: "r"(dst), "l"(W + (size_t)bkr[i] * N_ + bn0 + bnc));
    }
    asm volatile("cp.async.commit_group;");
#pragma unroll
    for (int i = 0; i < 2; i++) {
        As[(akc + 0) * ASTRIDE + amr[i]] = ra[i].x;
        As[(akc + 1) * ASTRIDE + amr[i]] = ra[i].y;
        As[(akc + 2) * ASTRIDE + amr[i]] = ra[i].z;
        As[(akc + 3) * ASTRIDE + amr[i]] = ra[i].w;
    }
    asm volatile("cp.async.wait_group 0;");
    __syncthreads();

    for (int kt = 0; kt < 16; kt++) {
        const int st = kt & 1;
        if (kt < 15) {
#pragma unroll
            for (int i = 0; i < 2; i++)
                ra[i] = *(const float4*)(A + (size_t)(bm + amr[i]) * NI_
                                           + (kt + 1) * 16 + akc);
#pragma unroll
            for (int i = 0; i < 2; i++) {
                unsigned dst = (unsigned)__cvta_generic_to_shared(
                    Bs + (st ^ 1) * (16 * 128) + bkr[i] * 128 + bnc);
                asm volatile("cp.async.cg.shared.global [%0], [%1], 16;"
                    :: "r"(dst),
                       "l"(W + (size_t)((kt+1)*16 + bkr[i]) * N_ + bn0 + bnc));
            }
            asm volatile("cp.async.commit_group;");
        }

        const float* as = As + st * (16 * ASTRIDE);
        const float* bs = Bs + st * (16 * 128);
#pragma unroll
        for (int k = 0; k < 16; k++) {
            ulonglong2 aA = *(const ulonglong2*)(as + k * ASTRIDE + m0);
            ulonglong2 aB = *(const ulonglong2*)(as + k * ASTRIDE + m0 + 4);
            unsigned long long am4[4] = { aA.x, aA.y, aB.x, aB.y };
            float4 bv0 = *(const float4*)(bs + k * 128 + (tn << 2));
            float4 bv1 = *(const float4*)(bs + k * 128 + 64 + (tn << 2));
            unsigned long long b[8];
            PACK2(b[0], bv0.x); PACK2(b[1], bv0.y);
            PACK2(b[2], bv0.z); PACK2(b[3], bv0.w);
            PACK2(b[4], bv1.x); PACK2(b[5], bv1.y);
            PACK2(b[6], bv1.z); PACK2(b[7], bv1.w);
#pragma unroll
            for (int e = 0; e < 4; e++)
#pragma unroll
                for (int j = 0; j < 8; j++)
                    FFMA2(acc[e][j], am4[e], b[j], acc[e][j]);
        }
        if (kt == 15) break;

#pragma unroll
        for (int i = 0; i < 2; i++) {
            float* ad = As + (st ^ 1) * (16 * ASTRIDE);
            ad[(akc + 0) * ASTRIDE + amr[i]] = ra[i].x;
            ad[(akc + 1) * ASTRIDE + amr[i]] = ra[i].y;
            ad[(akc + 2) * ASTRIDE + amr[i]] = ra[i].z;
            ad[(akc + 3) * ASTRIDE + amr[i]] = ra[i].w;
        }
        asm volatile("cp.async.wait_group 0;");
        __syncthreads();
    }

    unsigned long long* op = g_xw;
    const int pbase = (bm + m0) >> 1;
#pragma unroll
    for (int e = 0; e < 4; e++) {
        size_t prow = (size_t)(pbase + e) * 256 + bn0;
        ulonglong2 s0, s1, s2, s3;
        s0.x = acc[e][0]; s0.y = acc[e][1];
        s1.x = acc[e][2]; s1.y = acc[e][3];
        s2.x = acc[e][4]; s2.y = acc[e][5];
        s3.x = acc[e][6]; s3.y = acc[e][7];
        *(ulonglong2*)(op + prow + (tn << 2))          = s0;
        *(ulonglong2*)(op + prow + (tn << 2) + 2)      = s1;
        *(ulonglong2*)(op + prow + 64 + (tn << 2))     = s2;
        *(ulonglong2*)(op + prow + 64 + (tn << 2) + 2) = s3;
    }
}

// ===========================================================================
// Kernel 2: warp-specialized LSNN scan. 128 CTAs x 512 threads.
//  Half 0 (tid<256, neuron n=tid): gather + dynamics + publish. Owns state.
//  Half 1 (tid>=256, n=tid-256): list build, dense high rows (220..255) +
//    xw(t+1) -> partial[n], v_sc + 4 output stores. All off recurrence path.
//  All staging arrays single-buffered (each is written on one side of a bar
//  and read on the other). 2 __syncthreads per step.
// ===========================================================================
#define WROWS 220
#define SENT  (220 << 10)
#define LCAP  252
// float offsets in smem
#define OFF_FLAT (221*256)
#define OFF_CNT  (OFF_FLAT + LCAP)          // 8 ints (7 used)
#define OFF_MASK (OFF_CNT + 8)              // 8 u32
#define OFF_TOT  (OFF_MASK + 8)             // 4 (1 used, pad to 16B)
#define OFF_ZHI  (OFF_TOT + 4)              // 36 floats (16B aligned)
#define OFF_DYNV (OFF_ZHI + 36)
#define OFF_DYNT (OFF_DYNV + 256)
#define OFF_PART (OFF_DYNT + 256)
#define SCAN_SMEM ((OFF_PART + 256) * 4)    // 230,608 B

__global__ void __launch_bounds__(512, 1)
lsnn_scan(const float* __restrict__ w_rec,
          const float* __restrict__ z0,  const float* __restrict__ v0,
          const float* __restrict__ a0,  const float* __restrict__ lsd0,
          float* __restrict__ out, float decay_v, float decay_a)
{
    extern __shared__ float sm[];
    float*    w_sm  = sm;                      // [221][256], row 220 = zeros
    int*      flatL = (int*)(sm + OFF_FLAT);   // [252]
    int*      cntS  = (int*)(sm + OFF_CNT);    // [8]
    unsigned* maskS = (unsigned*)(sm + OFF_MASK); // [8]
    int*      totS  = (int*)(sm + OFF_TOT);    // [1]
    float*    zhi   = sm + OFF_ZHI;            // [36]
    float*    dynV  = sm + OFF_DYNV;           // [256]
    float*    dynT  = sm + OFF_DYNT;           // [256]
    float*    part  = sm + OFF_PART;           // [256]

    const int tid  = threadIdx.x;
    const int half = tid >> 8;
    const int n    = tid & 255;
    const int w    = n >> 5;
    const int lane = n & 31;
    const int b    = blockIdx.x;

    // weights rows 0..219 -> smem (all 512 threads)
    {
        const float4* src = (const float4*)w_rec;
        float4*       dst = (float4*)w_sm;
        for (int i = tid; i < WROWS * 64; i += 512) dst[i] = src[i];
    }
    // half1: rows 220..255 packed register pairs (18 x f32x2), diag masked
    unsigned long long wp[18];
    if (half == 1) {
#pragma unroll
        for (int j = 0; j < 18; j++) {
            float wlo = w_rec[(size_t)(220 + 2*j) * 256 + n];
            float whi = w_rec[(size_t)(221 + 2*j) * 256 + n];
            if (n == 220 + 2*j) wlo = 0.f;
            if (n == 221 + 2*j) whi = 0.f;
            PACKAB(wp[j], wlo, whi);
        }
    }
    if (half == 0) w_sm[WROWS * 256 + n] = 0.f;     // zero sentinel row
    if (tid < 8)  { cntS[tid] = 0; maskS[tid] = 0u; }
    if (tid == 8) totS[0] = 0;
    __syncthreads();
    if (tid < WROWS) w_sm[tid * 256 + tid] = 0.f;   // diag mask for smem rows

    const float omdv = 1.f - decay_v;
    const float omda = 1.f - decay_a;
    const char*  wpn = (const char*)w_sm + (n << 2);
    const float* xwb = (const float*)g_xw;
    const int    mb0 = b * T_;
    const int    twon = n << 1;
#define XW_LD(tt_) __ldcs(xwb + (((size_t)((mb0 + (tt_)) >> 1)) << 9) + twon + ((mb0 + (tt_)) & 1))

    // ---- state (half 0 only) ----
    float z_self = 0.f, v = 0.f, a = 0.f, lsd = 0.f;
    float xw1 = 0.f, xw2 = 0.f;      // half1 xw pipeline: xw(t+1), xw(t+2)

    // ---- init: publish z0 spikes, then half1 builds list + partial(0) ----
    if (half == 0) {
        z_self = z0[b * N_ + n];  v   = v0[b * N_ + n];
        a      = a0[b * N_ + n];  lsd = lsd0[b * N_ + n];
        unsigned m    = __ballot_sync(0xffffffffu, z_self != 0.f);
        unsigned mseg = (w == 6) ? (m & 0x0FFFFFFFu) : m;
        if (lane == 0) { maskS[w] = m; if (w < 7) cntS[w] = __popc(mseg); }
        if (n >= WROWS) zhi[n - WROWS] = z_self;
    }
    __syncthreads();
    if (half == 1) {
        int4 cA = *(const int4*)&cntS[0];
        int4 cB = *(const int4*)&cntS[4];
        unsigned mm   = maskS[w];
        unsigned mseg = (w == 6) ? (mm & 0x0FFFFFFFu) : mm;
        if (w < 7) {
            int start = 0;
            if (w > 0) start += cA.x; if (w > 1) start += cA.y;
            if (w > 2) start += cA.z; if (w > 3) start += cA.w;
            if (w > 4) start += cB.x; if (w > 5) start += cB.y;
            if ((mseg >> lane) & 1u) {
                int r = __popc(mseg & ((1u << lane) - 1u));
                flatL[start + r] = n << 10;
            }
        } else {
            int tt = cA.x + cA.y + cA.z + cA.w + cB.x + cB.y + cB.z;
            if (lane < 8 || tt + lane < 32) flatL[tt + lane] = SENT;
            if (lane == 0) totS[0] = tt;
        }
        // partial(0) = dense(z0 high) + xw(0)
        unsigned long long hp; PACKAB(hp, 0.f, 0.f);
        const float4* z4 = (const float4*)zhi;
#pragma unroll
        for (int i = 0; i < 9; i++) {
            float4 q = z4[i];
            unsigned long long zlo, zhi2;
            PACKAB(zlo, q.x, q.y); PACKAB(zhi2, q.z, q.w);
            FFMA2(hp, zlo, wp[2*i],   hp);
            FFMA2(hp, zhi2, wp[2*i+1], hp);
        }
        float2 hv = *(float2*)&hp;
        part[n] = __fadd_rn(__fadd_rn(hv.x, hv.y), XW_LD(0));
        xw1 = XW_LD(1);
        xw2 = XW_LD(2);
    }
    __syncthreads();

#pragma unroll 1
    for (int t = 0; t < T_; t++) {
        float xw3 = 0.f;
        if (half == 0) {
            // ---- phase 1: gather + dynamics + publish ----
            const int  tot = totS[0];
            const int4* fc = (const int4*)flatL;
            int4 c0 = fc[0], c1 = fc[1], c2 = fc[2], c3 = fc[3];
            int4 c4 = fc[4], c5 = fc[5], c6 = fc[6], c7 = fc[7];
            float pr = part[n];

            float av[8];
#pragma unroll
            for (int j = 0; j < 8; j++) av[j] = 0.f;

            av[0] += *(const float*)(wpn + c0.x);
            av[1] += *(const float*)(wpn + c0.y);
            av[2] += *(const float*)(wpn + c0.z);
            av[3] += *(const float*)(wpn + c0.w);
            av[4] += *(const float*)(wpn + c1.x);
            av[5] += *(const float*)(wpn + c1.y);
            av[6] += *(const float*)(wpn + c1.z);
            av[7] += *(const float*)(wpn + c1.w);
            av[0] += *(const float*)(wpn + c2.x);
            av[1] += *(const float*)(wpn + c2.y);
            av[2] += *(const float*)(wpn + c2.z);
            av[3] += *(const float*)(wpn + c2.w);
            av[4] += *(const float*)(wpn + c3.x);
            av[5] += *(const float*)(wpn + c3.y);
            av[6] += *(const float*)(wpn + c3.z);
            av[7] += *(const float*)(wpn + c3.w);
            av[0] += *(const float*)(wpn + c4.x);
            av[1] += *(const float*)(wpn + c4.y);
            av[2] += *(const float*)(wpn + c4.z);
            av[3] += *(const float*)(wpn + c4.w);
            av[4] += *(const float*)(wpn + c5.x);
            av[5] += *(const float*)(wpn + c5.y);
            av[6] += *(const float*)(wpn + c5.z);
            av[7] += *(const float*)(wpn + c5.w);
            av[0] += *(const float*)(wpn + c6.x);
            av[1] += *(const float*)(wpn + c6.y);
            av[2] += *(const float*)(wpn + c6.z);
            av[3] += *(const float*)(wpn + c6.w);
            av[4] += *(const float*)(wpn + c7.x);
            av[5] += *(const float*)(wpn + c7.y);
            av[6] += *(const float*)(wpn + c7.z);
            av[7] += *(const float*)(wpn + c7.w);

#pragma unroll 1
            for (int j = 32; j < tot; j += 4) {
                int4 o = *(const int4*)(flatL + j);
                av[0] += *(const float*)(wpn + o.x);
                av[1] += *(const float*)(wpn + o.y);
                av[2] += *(const float*)(wpn + o.z);
                av[3] += *(const float*)(wpn + o.w);
            }

            const float i_in = __fadd_rn(pr,
                __fadd_rn(__fadd_rn(__fadd_rn(av[0], av[1]),
                                    __fadd_rn(av[2], av[3])),
                          __fadd_rn(__fadd_rn(av[4], av[5]),
                                    __fadd_rn(av[6], av[7]))));

            float new_a = __fadd_rn(__fmul_rn(decay_a, a),
                                    __fmul_rn(omda, z_self));
            float thr   = __fadd_rn(0.03f, __fmul_rn(new_a, 1.8f));
            float new_v = __fadd_rn(
                            __fadd_rn(__fmul_rn(decay_v, v),
                                      __fmul_rn(omdv, i_in)),
                            __fmul_rn(-thr, z_self));
            int   spk = (new_v > thr) && (lsd >= 2.f);
            float zf  = spk ? 1.f : 0.f;

            unsigned m    = __ballot_sync(0xffffffffu, spk);
            unsigned mseg = (w == 6) ? (m & 0x0FFFFFFFu) : m;
            if (lane == 0) { maskS[w] = m; if (w < 7) cntS[w] = __popc(mseg); }
            if (n >= WROWS) zhi[n - WROWS] = zf;
            dynV[n] = new_v;
            dynT[n] = thr;

            float new_lsd = __fmul_rn(__fadd_rn(lsd, 1.f),
                                      __fadd_rn(1.f, -zf));
            z_self = zf; v = new_v; a = new_a; lsd = new_lsd;
        } else {
            xw3 = (t + 3 < T_) ? XW_LD(t + 3) : 0.f;
        }
        __syncthreads();    // bar C: publishes visible to half 1

        if (half == 1) {
            // ---- phase C: list build + partial(t+1) + outputs(t) ----
            int4 cA = *(const int4*)&cntS[0];
            int4 cB = *(const int4*)&cntS[4];
            unsigned mm   = maskS[w];
            unsigned mseg = (w == 6) ? (mm & 0x0FFFFFFFu) : mm;
            if (w < 7) {
                int start = 0;
                if (w > 0) start += cA.x; if (w > 1) start += cA.y;
                if (w > 2) start += cA.z; if (w > 3) start += cA.w;
                if (w > 4) start += cB.x; if (w > 5) start += cB.y;
                if ((mseg >> lane) & 1u) {
                    int r = __popc(mseg & ((1u << lane) - 1u));
                    flatL[start + r] = n << 10;
                }
            } else {
                int tt = cA.x + cA.y + cA.z + cA.w + cB.x + cB.y + cB.z;
                if (lane < 8 || tt + lane < 32) flatL[tt + lane] = SENT;
                if (lane == 0) totS[0] = tt;
            }

            // partial for step t+1 (dense high rows from zf(t) + xw(t+1))
            unsigned long long hp; PACKAB(hp, 0.f, 0.f);
            const float4* z4 = (const float4*)zhi;
#pragma unroll
            for (int i = 0; i < 9; i++) {
                float4 q = z4[i];
                unsigned long long zlo, zhi2;
                PACKAB(zlo, q.x, q.y); PACKAB(zhi2, q.z, q.w);
                FFMA2(hp, zlo, wp[2*i],   hp);
                FFMA2(hp, zhi2, wp[2*i+1], hp);
            }
            float2 hv = *(float2*)&hp;
            part[n] = __fadd_rn(__fadd_rn(hv.x, hv.y), xw1);
            xw1 = xw2; xw2 = xw3;

            // outputs of step t
            float nv = dynV[n], th = dynT[n];
            float pz = ((mm >> lane) & 1u) ? 1.f : 0.f;
            float vsc = __fdividef(__fadd_rn(nv, -th), th);
            const size_t ob = ((size_t)t * B_ + b) * N_ + n;
            __stcs(out + ob,            pz);
            __stcs(out + TBN_ + ob,     nv);
            __stcs(out + 2 * TBN_ + ob, th);
            __stcs(out + 3 * TBN_ + ob, vsc);
        }
        __syncthreads();    // bar A: list/partial visible to half 0
    }
#undef XW_LD
}

// ---------------------------------------------------------------------------
// Launcher (graph-capturable)
// ---------------------------------------------------------------------------
extern "C" void kernel_launch(void* const* d_in, const int* in_sizes, int n_in,
                              void* d_out, int out_size)
{
    const float* x     = (const float*)d_in[0];
    const float* w_in  = (const float*)d_in[1];
    const float* w_rec = (const float*)d_in[2];
    const float* z0    = (const float*)d_in[3];
    const float* v0    = (const float*)d_in[4];
    const float* a0    = (const float*)d_in[5];
    const float* lsd0  = (const float*)d_in[6];
    float* out = (float*)d_out;

    const float decay_v = expf(-1.0f / 20.0f);
    const float decay_a = expf(-1.0f / 20.0f);

    cudaFuncSetAttribute(gemm_xw,
                         cudaFuncAttributeMaxDynamicSharedMemorySize, GEMM_SMEM);
    cudaFuncSetAttribute(lsnn_scan,
                         cudaFuncAttributeMaxDynamicSharedMemorySize, SCAN_SMEM);

    dim3 g1(M_ / 128, 2);
    gemm_xw<<<g1, 256, GEMM_SMEM>>>(x, w_in);
    lsnn_scan<<<B_, 512, SCAN_SMEM>>>(w_rec, z0, v0, a0, lsd0, out,
                                      decay_v, decay_a);
}

// round 9
// speedup vs baseline: 1.0885x; 1.0885x over previous
#include <cuda_runtime.h>
#include <math.h>

// Problem dims (fixed)
#define B_   128
#define T_   500
#define NI_  256
#define N_   256
#define M_   (B_*T_)
#define TBN_ ((size_t)T_*B_*N_)

// xw scratch, m-pair interleaved: ULL index p*256+n holds (xw[2p][n], xw[2p+1][n])
__device__ unsigned long long g_xw[(size_t)M_ * N_ / 2];
__device__ unsigned int g_ctr;      // work-stealing counter (reset per launch)

// Packed fp32x2 helpers
#define FFMA2(d, a, b, c) \
    asm("fma.rn.f32x2 %0, %1, %2, %3;" : "=l"(d) : "l"(a), "l"(b), "l"(c))
#define PACK2(d, s) \
    asm("mov.b64 %0, {%1, %1};" : "=l"(d) : "f"(s))
#define PACKAB(d, lo, hi) \
    asm("mov.b64 %0, {%1, %2};" : "=l"(d) : "f"(lo), "f"(hi))

// ===========================================================================
// Kernel 1: xw = x @ w_in. BM=128, BN=128, BK=16, 256 thr, 8m x 8n microtile.
// Persistent 296 CTAs (one resident wave, 2/SM) + atomic work-stealing over
// the 1000 tiles: removes the 3.38-wave quantization tail.
// ===========================================================================
#define ASTRIDE 132
#define ASZ (2*16*ASTRIDE)
#define BSZ (2*16*128)
#define GEMM_SMEM ((ASZ + BSZ) * 4)
#define NTILES 1000

__global__ void __launch_bounds__(256, 2)
gemm_xw(const float* __restrict__ A, const float* __restrict__ W)
{
    extern __shared__ float gsm[];
    float* As = gsm;
    float* Bs = gsm + ASZ;
    __shared__ int s_tile;

    const int t   = threadIdx.x;
    const int tn  = t & 15;
    const int m0  = (t >> 4) << 3;

    const int amr[2] = { (t) >> 2, (t + 256) >> 2 };
    const int akc    = (t & 3) << 2;
    const int bkr[2] = { t >> 5, (t + 256) >> 5 };
    const int bnc    = (t & 31) << 2;

    for (;;) {
        if (t == 0) s_tile = (int)atomicAdd(&g_ctr, 1u);
        __syncthreads();                 // s_tile visible + smem reuse safe
        const int tile = s_tile;
        __syncthreads();                 // allow next steal after read
        if (tile >= NTILES) break;

        const int bm  = (tile >> 1) << 7;
        const int bn0 = (tile & 1) << 7;

        unsigned long long acc[4][8];
#pragma unroll
        for (int e = 0; e < 4; e++)
#pragma unroll
            for (int j = 0; j < 8; j++) acc[e][j] = 0ull;

        float4 ra[2];

        // prologue: k-tile 0 into stage 0
#pragma unroll
        for (int i = 0; i < 2; i++)
            ra[i] = *(const float4*)(A + (size_t)(bm + amr[i]) * NI_ + akc);
#pragma unroll
        for (int i = 0; i < 2; i++) {
            unsigned dst = (unsigned)__cvta_generic_to_shared(Bs + bkr[i] * 128 + bnc);
            asm volatile("cp.async.cg.shared.global [%0], [%1], 16;"
                         :: "r"(dst), "l"(W + (size_t)bkr[i] * N_ + bn0 + bnc));
        }
        asm volatile("cp.async.commit_group;");
#pragma unroll
        for (int i = 0; i < 2; i++) {
            As[(akc + 0) * ASTRIDE + amr[i]] = ra[i].x;
            As[(akc + 1) * ASTRIDE + amr[i]] = ra[i].y;
            As[(akc + 2) * ASTRIDE + amr[i]] = ra[i].z;
            As[(akc + 3) * ASTRIDE + amr[i]] = ra[i].w;
        }
        asm volatile("cp.async.wait_group 0;");
        __syncthreads();

        for (int kt = 0; kt < 16; kt++) {
            const int st = kt & 1;
            if (kt < 15) {
#pragma unroll
                for (int i = 0; i < 2; i++)
                    ra[i] = *(const float4*)(A + (size_t)(bm + amr[i]) * NI_
                                               + (kt + 1) * 16 + akc);
#pragma unroll
                for (int i = 0; i < 2; i++) {
                    unsigned dst = (unsigned)__cvta_generic_to_shared(
                        Bs + (st ^ 1) * (16 * 128) + bkr[i] * 128 + bnc);
                    asm volatile("cp.async.cg.shared.global [%0], [%1], 16;"
                        :: "r"(dst),
                           "l"(W + (size_t)((kt+1)*16 + bkr[i]) * N_ + bn0 + bnc));
                }
                asm volatile("cp.async.commit_group;");
            }

            const float* as = As + st * (16 * ASTRIDE);
            const float* bs = Bs + st * (16 * 128);
#pragma unroll
            for (int k = 0; k < 16; k++) {
                ulonglong2 aA = *(const ulonglong2*)(as + k * ASTRIDE + m0);
                ulonglong2 aB = *(const ulonglong2*)(as + k * ASTRIDE + m0 + 4);
                unsigned long long am4[4] = { aA.x, aA.y, aB.x, aB.y };
                float4 bv0 = *(const float4*)(bs + k * 128 + (tn << 2));
                float4 bv1 = *(const float4*)(bs + k * 128 + 64 + (tn << 2));
                unsigned long long b[8];
                PACK2(b[0], bv0.x); PACK2(b[1], bv0.y);
                PACK2(b[2], bv0.z); PACK2(b[3], bv0.w);
                PACK2(b[4], bv1.x); PACK2(b[5], bv1.y);
                PACK2(b[6], bv1.z); PACK2(b[7], bv1.w);
#pragma unroll
                for (int e = 0; e < 4; e++)
#pragma unroll
                    for (int j = 0; j < 8; j++)
                        FFMA2(acc[e][j], am4[e], b[j], acc[e][j]);
            }
            if (kt == 15) break;

#pragma unroll
            for (int i = 0; i < 2; i++) {
                float* ad = As + (st ^ 1) * (16 * ASTRIDE);
                ad[(akc + 0) * ASTRIDE + amr[i]] = ra[i].x;
                ad[(akc + 1) * ASTRIDE + amr[i]] = ra[i].y;
                ad[(akc + 2) * ASTRIDE + amr[i]] = ra[i].z;
                ad[(akc + 3) * ASTRIDE + amr[i]] = ra[i].w;
            }
            asm volatile("cp.async.wait_group 0;");
            __syncthreads();
        }

        // epilogue: pair-interleaved g_xw
        unsigned long long* op = g_xw;
        const int pbase = (bm + m0) >> 1;
#pragma unroll
        for (int e = 0; e < 4; e++) {
            size_t prow = (size_t)(pbase + e) * 256 + bn0;
            ulonglong2 s0, s1, s2, s3;
            s0.x = acc[e][0]; s0.y = acc[e][1];
            s1.x = acc[e][2]; s1.y = acc[e][3];
            s2.x = acc[e][4]; s2.y = acc[e][5];
            s3.x = acc[e][6]; s3.y = acc[e][7];
            *(ulonglong2*)(op + prow + (tn << 2))          = s0;
            *(ulonglong2*)(op + prow + (tn << 2) + 2)      = s1;
            *(ulonglong2*)(op + prow + 64 + (tn << 2))     = s2;
            *(ulonglong2*)(op + prow + 64 + (tn << 2) + 2) = s3;
        }
        __syncthreads();   // epilogue reads of smem done before next tile fill
    }
}

// ===========================================================================
// Kernel 2: LSNN scan — R6 version, bit-identical (measured 261 us).
// ===========================================================================
#define WROWS 222
#define SENT  (222 << 10)
#define LCAP  232
#define OFF_FLAT (223*256)
#define OFF_CNT  (OFF_FLAT + 2*LCAP)
#define OFF_TOT  (OFF_CNT + 16)
#define OFF_ZHI  (OFF_TOT + 4)
#define SCAN_SMEM ((OFF_ZHI + 2*36) * 4)    // 230608 B

__global__ void __launch_bounds__(256, 1)
lsnn_scan(const float* __restrict__ w_rec,
          const float* __restrict__ z0,  const float* __restrict__ v0,
          const float* __restrict__ a0,  const float* __restrict__ lsd0,
          float* __restrict__ out, float decay_v, float decay_a)
{
    extern __shared__ float sm[];
    float* w_sm  = sm;                       // [223][256], row 222 = zeros
    int*   flatL = (int*)(sm + OFF_FLAT);    // [2][232]
    int*   cntS  = (int*)(sm + OFF_CNT);     // [2][8]
    int*   totS  = (int*)(sm + OFF_TOT);     // [2]
    float* zhi   = sm + OFF_ZHI;             // [2][36]

    const int b    = blockIdx.x;
    const int n    = threadIdx.x;
    const int w    = n >> 5;
    const int lane = n & 31;

    {
        const float4* src = (const float4*)w_rec;
        float4*       dst = (float4*)w_sm;
        for (int i = n; i < WROWS * 64; i += 256) dst[i] = src[i];
    }
    unsigned long long wp[17];
#pragma unroll
    for (int j = 0; j < 17; j++) {
        float wlo = w_rec[(size_t)(222 + 2*j) * 256 + n];
        float whi = w_rec[(size_t)(223 + 2*j) * 256 + n];
        if (n == 222 + 2*j) wlo = 0.f;
        if (n == 223 + 2*j) whi = 0.f;
        PACKAB(wp[j], wlo, whi);
    }
    w_sm[WROWS * 256 + n] = 0.f;
    if (n < 16) cntS[n] = 0;
    if (n < 2)  totS[n] = 0;
    if (n < 72) zhi[n] = 0.f;
    __syncthreads();
    if (n < WROWS) w_sm[n * 256 + n] = 0.f;

    float z_self = z0[b * N_ + n];
    float v      = v0[b * N_ + n];
    float a      = a0[b * N_ + n];
    float lsd    = lsd0[b * N_ + n];

    {
        unsigned m    = __ballot_sync(0xffffffffu, z_self != 0.f);
        unsigned mseg = (w == 6) ? (m & 0x3FFFFFFFu) : m;
        if (w < 7) { if (lane == 0) cntS[w] = __popc(mseg); }
        if (n >= 222) zhi[n - 222] = z_self;
        __syncthreads();
        int4 cA = *(const int4*)&cntS[0];
        int4 cB = *(const int4*)&cntS[4];
        if (w < 7) {
            int start = 0;
            if (w > 0) start += cA.x; if (w > 1) start += cA.y;
            if (w > 2) start += cA.z; if (w > 3) start += cA.w;
            if (w > 4) start += cB.x; if (w > 5) start += cB.y;
            if ((mseg >> lane) & 1u) {
                int r = __popc(mseg & ((1u << lane) - 1u));
                flatL[start + r] = n << 10;
            }
        }
        if (w == 7) {
            int tt = cA.x + cA.y + cA.z + cA.w + cB.x + cB.y + cB.z;
            if (lane < 8 || tt + lane < 32) flatL[tt + lane] = SENT;
            if (lane == 0) totS[0] = tt;
        }
    }

    const float omdv = 1.f - decay_v;
    const float omda = 1.f - decay_a;
    const char*  wpn = (const char*)w_sm + (n << 2);
    const float* xwb = (const float*)g_xw;
    const int    mb0 = b * T_;
    const int    twon = n << 1;

#define XW_LD(tt_) __ldcs(xwb + (((size_t)((mb0 + (tt_)) >> 1)) << 9) + twon + ((mb0 + (tt_)) & 1))
    float xw_c  = XW_LD(0);
    float xw_n1 = XW_LD(1);
    __syncthreads();

#pragma unroll 1
    for (int t = 0; t < T_; t++) {
        const int rb = t & 1, wb = rb ^ 1;

        float xw_n2 = (t + 2 < T_) ? XW_LD(t + 2) : 0.f;

        const int  tot = totS[rb];
        const int* fl  = flatL + rb * LCAP;
        const unsigned long long* zp =
            (const unsigned long long*)(zhi + rb * 36);

        const int4* fc = (const int4*)fl;
        int4 c0 = fc[0], c1 = fc[1], c2 = fc[2], c3 = fc[3];
        int4 c4 = fc[4], c5 = fc[5], c6 = fc[6], c7 = fc[7];

        float av[8];
#pragma unroll
        for (int j = 0; j < 8; j++) av[j] = 0.f;

        unsigned long long av2; PACKAB(av2, 0.f, 0.f);
#pragma unroll
        for (int j = 0; j < 17; j++) FFMA2(av2, zp[j], wp[j], av2);

        av[0] += *(const float*)(wpn + c0.x);
        av[1] += *(const float*)(wpn + c0.y);
        av[2] += *(const float*)(wpn + c0.z);
        av[3] += *(const float*)(wpn + c0.w);
        av[4] += *(const float*)(wpn + c1.x);
        av[5] += *(const float*)(wpn + c1.y);
        av[6] += *(const float*)(wpn + c1.z);
        av[7] += *(const float*)(wpn + c1.w);
        av[0] += *(const float*)(wpn + c2.x);
        av[1] += *(const float*)(wpn + c2.y);
        av[2] += *(const float*)(wpn + c2.z);
        av[3] += *(const float*)(wpn + c2.w);
        av[4] += *(const float*)(wpn + c3.x);
        av[5] += *(const float*)(wpn + c3.y);
        av[6] += *(const float*)(wpn + c3.z);
        av[7] += *(const float*)(wpn + c3.w);
        av[0] += *(const float*)(wpn + c4.x);
        av[1] += *(const float*)(wpn + c4.y);
        av[2] += *(const float*)(wpn + c4.z);
        av[3] += *(const float*)(wpn + c4.w);
        av[4] += *(const float*)(wpn + c5.x);
        av[5] += *(const float*)(wpn + c5.y);
        av[6] += *(const float*)(wpn + c5.z);
        av[7] += *(const float*)(wpn + c5.w);
        av[0] += *(const float*)(wpn + c6.x);
        av[1] += *(const float*)(wpn + c6.y);
        av[2] += *(const float*)(wpn + c6.z);
        av[3] += *(const float*)(wpn + c6.w);
        av[4] += *(const float*)(wpn + c7.x);
        av[5] += *(const float*)(wpn + c7.y);
        av[6] += *(const float*)(wpn + c7.z);
        av[7] += *(const float*)(wpn + c7.w);

#pragma unroll 1
        for (int j = 32; j < tot; j += 4) {
            int4 o = *(const int4*)(fl + j);
            av[0] += *(const float*)(wpn + o.x);
            av[1] += *(const float*)(wpn + o.y);
            av[2] += *(const float*)(wpn + o.z);
            av[3] += *(const float*)(wpn + o.w);
        }

        float2 hv = *(float2*)&av2;
        const float i_in = __fadd_rn(__fadd_rn(xw_c, __fadd_rn(hv.x, hv.y)),
            __fadd_rn(__fadd_rn(__fadd_rn(av[0], av[1]), __fadd_rn(av[2], av[3])),
                      __fadd_rn(__fadd_rn(av[4], av[5]), __fadd_rn(av[6], av[7]))));

        float new_a = __fadd_rn(__fmul_rn(decay_a, a), __fmul_rn(omda, z_self));
        float thr   = __fadd_rn(0.03f, __fmul_rn(new_a, 1.8f));
        float new_v = __fadd_rn(
                        __fadd_rn(__fmul_rn(decay_v, v), __fmul_rn(omdv, i_in)),
                        __fmul_rn(-thr, z_self));
        int   spk = (new_v > thr) && (lsd >= 2.f);
        float zf  = spk ? 1.f : 0.f;

        unsigned m    = __ballot_sync(0xffffffffu, spk);
        unsigned mseg = (w == 6) ? (m & 0x3FFFFFFFu) : m;
        if (w < 7) { if (lane == 0) cntS[wb * 8 + w] = __popc(mseg); }
        if (n >= 222) zhi[wb * 36 + (n - 222)] = zf;

        float new_lsd = __fmul_rn(__fadd_rn(lsd, 1.f), __fadd_rn(1.f, -zf));
        float v_sc    = __fdividef(__fadd_rn(new_v, -thr), thr);
        __syncthreads();

        const size_t ob = ((size_t)t * B_ + b) * N_ + n;
        __stcs(out + ob,            zf);
        __stcs(out + TBN_ + ob,     new_v);
        __stcs(out + 2 * TBN_ + ob, thr);
        __stcs(out + 3 * TBN_ + ob, v_sc);

        {
            int4 cA = *(const int4*)&cntS[wb * 8];
            int4 cB = *(const int4*)&cntS[wb * 8 + 4];
            if (w < 7) {
                int start = 0;
                if (w > 0) start += cA.x; if (w > 1) start += cA.y;
                if (w > 2) start += cA.z; if (w > 3) start += cA.w;
                if (w > 4) start += cB.x; if (w > 5) start += cB.y;
                if ((mseg >> lane) & 1u) {
                    int r = __popc(mseg & ((1u << lane) - 1u));
                    flatL[wb * LCAP + start + r] = n << 10;
                }
            } else {
                int tt = cA.x + cA.y + cA.z + cA.w + cB.x + cB.y + cB.z;
                if (lane < 8 || tt + lane < 32)
                    flatL[wb * LCAP + tt + lane] = SENT;
                if (lane == 0) totS[wb] = tt;
            }
        }

        z_self = zf; v = new_v; a = new_a; lsd = new_lsd;
        xw_c = xw_n1; xw_n1 = xw_n2;
        __syncthreads();
    }
#undef XW_LD
}

// ---------------------------------------------------------------------------
// Launcher (graph-capturable: launches + async memset only)
// ---------------------------------------------------------------------------
extern "C" void kernel_launch(void* const* d_in, const int* in_sizes, int n_in,
                              void* d_out, int out_size)
{
    const float* x     = (const float*)d_in[0];
    const float* w_in  = (const float*)d_in[1];
    const float* w_rec = (const float*)d_in[2];
    const float* z0    = (const float*)d_in[3];
    const float* v0    = (const float*)d_in[4];
    const float* a0    = (const float*)d_in[5];
    const float* lsd0  = (const float*)d_in[6];
    float* out = (float*)d_out;

    const float decay_v = expf(-1.0f / 20.0f);
    const float decay_a = expf(-1.0f / 20.0f);

    cudaFuncSetAttribute(gemm_xw,
                         cudaFuncAttributeMaxDynamicSharedMemorySize, GEMM_SMEM);
    cudaFuncSetAttribute(lsnn_scan,
                         cudaFuncAttributeMaxDynamicSharedMemorySize, SCAN_SMEM);

    // reset work-stealing counter (graph-capturable async memset)
    void* ctr_addr = nullptr;
    cudaGetSymbolAddress(&ctr_addr, g_ctr);
    cudaMemsetAsync(ctr_addr, 0, sizeof(unsigned int));

    gemm_xw<<<296, 256, GEMM_SMEM>>>(x, w_in);
    lsnn_scan<<<B_, 256, SCAN_SMEM>>>(w_rec, z0, v0, a0, lsd0, out,
                                      decay_v, decay_a);
}